// round 8
// baseline (speedup 1.0000x reference)
#include <cuda_runtime.h>
#include <cuda_bf16.h>
#include <math.h>
#include <stdint.h>

// Problem constants
#define Nb   4          // batch
#define Tt   4096       // sequence length
#define Dd   512        // model dim
#define Hh   8          // heads
#define NHh  4          // hash rounds
#define BSs  64         // bucket chunk size
#define DHh  64         // head dim
#define NBb  64         // n_buckets
#define CSs  256        // chunks = NH * NB
#define Ll   16384      // NH * T

// ---------------- scratch (device globals; no allocation allowed) ----------
__device__ float g_Q[(size_t)Nb * Tt * Dd];                 // 33.5 MB
__device__ float g_V[(size_t)Nb * Tt * Dd];                 // 33.5 MB
__device__ int   g_buckets[(size_t)Nb * Hh * NHh * Tt];     // 2 MB
__device__ int   g_perm[(size_t)Nb * Hh * Ll];              // 2 MB
__device__ float g_O[(size_t)Nb * Hh * NHh * Tt * DHh];     // 134 MB
__device__ float g_logits[(size_t)Nb * Hh * NHh * Tt];      // 2 MB
__device__ __nv_bfloat16 g_wthi[Dd * Dd];                   // 0.5 MB (W_V^T hi)
__device__ __nv_bfloat16 g_wtlo[Dd * Dd];                   // 0.5 MB (W_V^T lo)

// ================= helpers ==================================================
__device__ __forceinline__ uint32_t smem_u32(const void* p) {
    uint32_t a;
    asm("{ .reg .u64 t; cvta.to.shared.u64 t, %1; cvt.u32.u64 %0, t; }" : "=r"(a) : "l"(p));
    return a;
}
#define MMA_BF16(d, a, b)                                                     \
    asm volatile("mma.sync.aligned.m16n8k16.row.col.f32.bf16.bf16.f32 "       \
        "{%0,%1,%2,%3}, {%4,%5,%6,%7}, {%8,%9}, {%0,%1,%2,%3};"               \
        : "+f"((d)[0]), "+f"((d)[1]), "+f"((d)[2]), "+f"((d)[3])              \
        : "r"((a)[0]), "r"((a)[1]), "r"((a)[2]), "r"((a)[3]),                 \
          "r"((b)[0]), "r"((b)[1]))
#define LDSM4(r0, r1, r2, r3, addr)                                           \
    asm volatile("ldmatrix.sync.aligned.m8n8.x4.shared.b16 {%0,%1,%2,%3}, [%4];" \
        : "=r"(r0), "=r"(r1), "=r"(r2), "=r"(r3) : "r"(addr))
#define LDSM4T(r0, r1, r2, r3, addr)                                          \
    asm volatile("ldmatrix.sync.aligned.m8n8.x4.trans.shared.b16 {%0,%1,%2,%3}, [%4];" \
        : "=r"(r0), "=r"(r1), "=r"(r2), "=r"(r3) : "r"(addr))

// ================= Q GEMM: fp32 SIMT (exact path for bucketing) =============
__global__ __launch_bounds__(256, 2)
void gemm_q_kernel(const float* __restrict__ A,
                   const float* __restrict__ W, const float* __restrict__ bias)
{
    __shared__ float As[16][132];
    __shared__ float Bs[16][132];

    const int tid = threadIdx.x;
    const int tx = tid & 15, ty = tid >> 4;
    const int rowBase = blockIdx.y * 128;
    const int colBase = blockIdx.x * 128;

    float acc[8][8];
#pragma unroll
    for (int i = 0; i < 8; i++)
#pragma unroll
        for (int j = 0; j < 8; j++) acc[i][j] = 0.f;

    for (int kt = 0; kt < Dd; kt += 16) {
#pragma unroll
        for (int l = 0; l < 2; l++) {
            int e = tid + l * 256;
            int r = e >> 2, c4 = e & 3;
            float4 v = *(const float4*)&A[(size_t)(rowBase + r) * Dd + kt + c4 * 4];
            As[c4 * 4 + 0][r] = v.x;
            As[c4 * 4 + 1][r] = v.y;
            As[c4 * 4 + 2][r] = v.z;
            As[c4 * 4 + 3][r] = v.w;
        }
#pragma unroll
        for (int l = 0; l < 2; l++) {
            int e = tid + l * 256;
            int r = e >> 5, c4 = e & 31;
            float4 v = *(const float4*)&W[(size_t)(kt + r) * Dd + colBase + c4 * 4];
            *(float4*)&Bs[r][c4 * 4] = v;
        }
        __syncthreads();
#pragma unroll
        for (int k = 0; k < 16; k++) {
            float a[8], b[8];
            *(float4*)&a[0] = *(const float4*)&As[k][ty * 8];
            *(float4*)&a[4] = *(const float4*)&As[k][ty * 8 + 4];
            *(float4*)&b[0] = *(const float4*)&Bs[k][tx * 8];
            *(float4*)&b[4] = *(const float4*)&Bs[k][tx * 8 + 4];
#pragma unroll
            for (int i = 0; i < 8; i++)
#pragma unroll
                for (int j = 0; j < 8; j++) acc[i][j] += a[i] * b[j];
        }
        __syncthreads();
    }
#pragma unroll
    for (int i = 0; i < 8; i++) {
        const int row = rowBase + ty * 8 + i;
#pragma unroll
        for (int j4 = 0; j4 < 2; j4++) {
            const int col = colBase + tx * 8 + j4 * 4;
            float4 o;
            o.x = acc[i][j4 * 4 + 0] + bias[col + 0];
            o.y = acc[i][j4 * 4 + 1] + bias[col + 1];
            o.z = acc[i][j4 * 4 + 2] + bias[col + 2];
            o.w = acc[i][j4 * 4 + 3] + bias[col + 3];
            *(float4*)&g_Q[(size_t)row * Dd + col] = o;
        }
    }
}

// ================= split + transpose W_V ====================================
__global__ void split_w_kernel(const float* __restrict__ W)
{
    __shared__ float tile[32][33];
    const int bx = blockIdx.x * 32;   // n block
    const int by = blockIdx.y * 32;   // k block
    const int tx = threadIdx.x, ty = threadIdx.y;   // 32 x 8
#pragma unroll
    for (int r = 0; r < 32; r += 8)
        tile[ty + r][tx] = W[(size_t)(by + ty + r) * Dd + bx + tx];
    __syncthreads();
#pragma unroll
    for (int r = 0; r < 32; r += 8) {
        float val = tile[tx][ty + r];
        __nv_bfloat16 hi = __float2bfloat16(val);
        __nv_bfloat16 lo = __float2bfloat16(val - __bfloat162float(hi));
        size_t o = (size_t)(bx + ty + r) * Dd + by + tx;
        g_wthi[o] = hi;
        g_wtlo[o] = lo;
    }
}

// ================= V GEMM: mma.sync bf16 3-term, 128x128 tile ==============
#define PITCH 40
#define A_HI  0
#define A_LO  (128 * PITCH)
#define B_HI  (2 * 128 * PITCH)
#define B_LO  (3 * 128 * PITCH)
#define SMEM_MMA (4 * 128 * PITCH * 2)

__global__ __launch_bounds__(256, 2)
void gemm_v_kernel(const float* __restrict__ x, const float* __restrict__ bias)
{
    extern __shared__ uint16_t sm16[];
    const int tid = threadIdx.x;
    const int wid = tid >> 5, lane = tid & 31;
    const int g = lane >> 2, tg = lane & 3;
    const int wm = wid & 3, wn = wid >> 2;          // 4m x 2n warps
    const int mbase = blockIdx.y * 128;
    const int ncol0 = blockIdx.x * 128;

    float acc[2][8][4];
#pragma unroll
    for (int i = 0; i < 2; i++)
#pragma unroll
        for (int j = 0; j < 8; j++)
#pragma unroll
            for (int k = 0; k < 4; k++) acc[i][j][k] = 0.f;

    for (int slab = 0; slab < 16; slab++) {
        const int kt = slab * 32;
#pragma unroll
        for (int i = 0; i < 4; i++) {
            const int e = tid + i * 256;            // [0,1024)
            const int m = e >> 3, k4 = e & 7;
            float4 v = *(const float4*)&x[(size_t)(mbase + m) * Dd + kt + k4 * 4];
            __nv_bfloat162 h01 = __floats2bfloat162_rn(v.x, v.y);
            __nv_bfloat162 h23 = __floats2bfloat162_rn(v.z, v.w);
            __nv_bfloat162 l01 = __floats2bfloat162_rn(v.x - __low2float(h01),
                                                       v.y - __high2float(h01));
            __nv_bfloat162 l23 = __floats2bfloat162_rn(v.z - __low2float(h23),
                                                       v.w - __high2float(h23));
            const int off = m * PITCH + k4 * 4;
            *(__nv_bfloat162*)(sm16 + A_HI + off)     = h01;
            *(__nv_bfloat162*)(sm16 + A_HI + off + 2) = h23;
            *(__nv_bfloat162*)(sm16 + A_LO + off)     = l01;
            *(__nv_bfloat162*)(sm16 + A_LO + off + 2) = l23;
        }
#pragma unroll
        for (int i = 0; i < 4; i++) {
            const int e = tid + i * 256;            // [0,1024)
            const int split = e >> 9;
            const int r = (e >> 2) & 127;
            const int k8 = e & 3;
            const __nv_bfloat16* src = (split ? g_wtlo : g_wthi)
                + (size_t)(ncol0 + r) * Dd + kt + k8 * 8;
            *(uint4*)(sm16 + (split ? B_LO : B_HI) + r * PITCH + k8 * 8)
                = *(const uint4*)src;
        }
        __syncthreads();

#pragma unroll
        for (int kk = 0; kk < 32; kk += 16) {
            uint32_t ah[2][4], al[2][4];
#pragma unroll
            for (int mt = 0; mt < 2; mt++) {
                const int ro = (wm * 32 + mt * 16 + g) * PITCH + kk + 2 * tg;
                ah[mt][0] = *(const uint32_t*)(sm16 + A_HI + ro);
                ah[mt][1] = *(const uint32_t*)(sm16 + A_HI + ro + 8 * PITCH);
                ah[mt][2] = *(const uint32_t*)(sm16 + A_HI + ro + 8);
                ah[mt][3] = *(const uint32_t*)(sm16 + A_HI + ro + 8 * PITCH + 8);
                al[mt][0] = *(const uint32_t*)(sm16 + A_LO + ro);
                al[mt][1] = *(const uint32_t*)(sm16 + A_LO + ro + 8 * PITCH);
                al[mt][2] = *(const uint32_t*)(sm16 + A_LO + ro + 8);
                al[mt][3] = *(const uint32_t*)(sm16 + A_LO + ro + 8 * PITCH + 8);
            }
#pragma unroll
            for (int ng = 0; ng < 2; ng++) {
                uint32_t bh[4][2], bl[4][2];
#pragma unroll
                for (int q = 0; q < 4; q++) {
                    const int ro = (wn * 64 + (ng * 4 + q) * 8 + g) * PITCH + kk + 2 * tg;
                    bh[q][0] = *(const uint32_t*)(sm16 + B_HI + ro);
                    bh[q][1] = *(const uint32_t*)(sm16 + B_HI + ro + 8);
                    bl[q][0] = *(const uint32_t*)(sm16 + B_LO + ro);
                    bl[q][1] = *(const uint32_t*)(sm16 + B_LO + ro + 8);
                }
                // sweeps: per-accumulator order stays hh, hl, lh
#pragma unroll
                for (int mt = 0; mt < 2; mt++)
#pragma unroll
                    for (int q = 0; q < 4; q++)
                        MMA_BF16(acc[mt][ng * 4 + q], ah[mt], bh[q]);
#pragma unroll
                for (int mt = 0; mt < 2; mt++)
#pragma unroll
                    for (int q = 0; q < 4; q++)
                        MMA_BF16(acc[mt][ng * 4 + q], ah[mt], bl[q]);
#pragma unroll
                for (int mt = 0; mt < 2; mt++)
#pragma unroll
                    for (int q = 0; q < 4; q++)
                        MMA_BF16(acc[mt][ng * 4 + q], al[mt], bh[q]);
            }
        }
        __syncthreads();
    }

#pragma unroll
    for (int mt = 0; mt < 2; mt++) {
        const int r0 = mbase + wm * 32 + mt * 16 + g;
#pragma unroll
        for (int nt = 0; nt < 8; nt++) {
            const int col = ncol0 + wn * 64 + nt * 8 + 2 * tg;
            float2 b2 = *(const float2*)&bias[col];
            float2 o0, o1;
            o0.x = acc[mt][nt][0] + b2.x;
            o0.y = acc[mt][nt][1] + b2.y;
            o1.x = acc[mt][nt][2] + b2.x;
            o1.y = acc[mt][nt][3] + b2.y;
            *(float2*)&g_V[(size_t)r0 * Dd + col] = o0;
            *(float2*)&g_V[(size_t)(r0 + 8) * Dd + col] = o1;
        }
    }
}

// ================= bucket kernel: rotation GEMM + fused argmax ==============
#define AsP 68
#define BsP 132
#define SMEM_BKT ((128 * AsP + 64 * BsP) * 4)

__global__ __launch_bounds__(256, 2)
void bucket_kernel(const float* __restrict__ rot)
{
    extern __shared__ float smf[];
    float* As = smf;                  // [128 m][68 k]
    float* Bs = smf + 128 * AsP;      // [64 k][132 c]

    const int h = blockIdx.y, n = blockIdx.z;
    const int tid = threadIdx.x;      // 256
    const int tx = tid & 15, ty = tid >> 4;
    const int t0 = blockIdx.x * 128;

    const float* Qb = g_Q + ((size_t)n * Tt + t0) * Dd + h * DHh;
#pragma unroll
    for (int l = 0; l < 8; l++) {
        const int e = tid + l * 256;
        const int r = e >> 4, c4 = e & 15;
        *(float4*)&As[r * AsP + c4 * 4] = *(const float4*)&Qb[(size_t)r * Dd + c4 * 4];
    }
    const float* Rb = rot + (size_t)h * 8192;
#pragma unroll
    for (int l = 0; l < 8; l++) {
        const int e = tid + l * 256;
        const int kr = e >> 5, c4 = e & 31;
        *(float4*)&Bs[kr * BsP + c4 * 4] = *(const float4*)&Rb[kr * 128 + c4 * 4];
    }
    __syncthreads();

    float acc[8][8];
#pragma unroll
    for (int i = 0; i < 8; i++)
#pragma unroll
        for (int j = 0; j < 8; j++) acc[i][j] = 0.f;

#pragma unroll 4
    for (int k = 0; k < 64; k++) {
        float a[8], b[8];
#pragma unroll
        for (int i = 0; i < 8; i++) a[i] = As[(ty * 8 + i) * AsP + k];
        *(float4*)&b[0] = *(const float4*)&Bs[k * BsP + tx * 8];
        *(float4*)&b[4] = *(const float4*)&Bs[k * BsP + tx * 8 + 4];
#pragma unroll
        for (int i = 0; i < 8; i++)
#pragma unroll
            for (int j = 0; j < 8; j++) acc[i][j] += a[i] * b[j];
    }

    const int ig = (tx & 3) * 8;
    const int r = tx >> 2;
#pragma unroll
    for (int i = 0; i < 8; i++) {
        float bv = acc[i][0];
        int bidx = ig;
#pragma unroll
        for (int j = 1; j < 8; j++)
            if (acc[i][j] > bv) { bv = acc[i][j]; bidx = ig + j; }
#pragma unroll
        for (int j = 0; j < 8; j++)
            if (-acc[i][j] > bv) { bv = -acc[i][j]; bidx = 32 + ig + j; }

        float ov; int oi;
        ov = __shfl_xor_sync(0xffffffffu, bv, 1);
        oi = __shfl_xor_sync(0xffffffffu, bidx, 1);
        if (ov > bv || (ov == bv && oi < bidx)) { bv = ov; bidx = oi; }
        ov = __shfl_xor_sync(0xffffffffu, bv, 2);
        oi = __shfl_xor_sync(0xffffffffu, bidx, 2);
        if (ov > bv || (ov == bv && oi < bidx)) { bv = ov; bidx = oi; }

        if ((tx & 3) == 0)
            g_buckets[(((size_t)n * Hh + h) * NHh + r) * Tt + t0 + ty * 8 + i]
                = bidx + r * NBb;
    }
}

// ================= segmented stable counting sort per (n,h) =================
#define HROW 258
#define SMEM_SORT (Ll + 256 * HROW * 2 + 256 * 4)
__global__ void sort_kernel()
{
    extern __shared__ char smraw[];
    unsigned char*  sb   = (unsigned char*)smraw;
    unsigned short* hist = (unsigned short*)(smraw + Ll);
    int*            base = (int*)(smraw + Ll + 256 * HROW * 2);
    __shared__ int tot[256];

    const int nh = blockIdx.x;
    const int tid = threadIdx.x;

    for (int e = tid; e < 256 * HROW / 2; e += 256)
        ((unsigned int*)hist)[e] = 0;
    __syncthreads();

    const int* bptr = g_buckets + (size_t)nh * Ll;
    for (int e = tid; e < Ll; e += 256)
        sb[e] = (unsigned char)bptr[e];
    __syncthreads();

    {
        const int s = tid;
#pragma unroll 4
        for (int j = 0; j < 64; j++) {
            int b = sb[s * 64 + j];
            hist[b * HROW + s]++;
        }
    }
    __syncthreads();

    {
        const unsigned short* row = &hist[tid * HROW];
        int sum = 0;
#pragma unroll 8
        for (int s2 = 0; s2 < 256; s2++) sum += row[s2];
        tot[tid] = sum;
    }
    __syncthreads();
    if (tid == 0) {
        int run = 0;
        for (int b = 0; b < 256; b++) { base[b] = run; run += tot[b]; }
    }
    __syncthreads();

    {
        unsigned short* row = &hist[tid * HROW];
        unsigned short run = 0;
        for (int s2 = 0; s2 < 256; s2++) {
            unsigned short v = row[s2];
            row[s2] = run;
            run = (unsigned short)(run + v);
        }
    }
    __syncthreads();

    {
        const int s = tid;
        int* pout = g_perm + (size_t)nh * Ll;
        for (int j = 0; j < 64; j++) {
            int i = s * 64 + j;
            int b = sb[i];
            unsigned short off = hist[b * HROW + s];
            hist[b * HROW + s] = (unsigned short)(off + 1);
            pout[base[b] + off] = (b << 16) | i;
        }
    }
}

// ================= chunked attention (mma + ldmatrix, sweep-ordered) ========
#define KHP 72
#define VP  72
#define OKH_HI 0
#define OKH_LO 18432
#define OV_HI  36864
#define OV_LO  55296
#define OMETA  73728
#define ORSC   74240
#define OINVS  74496
#define ORNORM 74752
#define SMEM_ATT3 75264

__global__ __launch_bounds__(128, 3)
void attention_kernel()
{
    extern __shared__ char smb[];
    __nv_bfloat16* kh_hi = (__nv_bfloat16*)(smb + OKH_HI);   // [128][72]
    __nv_bfloat16* kh_lo = (__nv_bfloat16*)(smb + OKH_LO);
    __nv_bfloat16* v_hi  = (__nv_bfloat16*)(smb + OV_HI);    // [128][72]
    __nv_bfloat16* v_lo  = (__nv_bfloat16*)(smb + OV_LO);
    int*   pmeta = (int*)(smb + OMETA);                      // 128
    float* rsc   = (float*)(smb + ORSC);                     // 64
    float* invs  = (float*)(smb + OINVS);                    // 64
    float* rnorm = (float*)(smb + ORNORM);                   // 128

    const int c = blockIdx.x, h = blockIdx.y, n = blockIdx.z;
    const int tid = threadIdx.x;
    const int pc = (c + CSs - 1) % CSs;

    {
        const int p = (tid < 64) ? (c * BSs + tid) : (pc * BSs + (tid - 64));
        pmeta[tid] = g_perm[((size_t)n * Hh + h) * Ll + p];
    }
    __syncthreads();

    const float* Qb = g_Q + (size_t)n * Tt * Dd + h * DHh;
    const float* Vb = g_V + (size_t)n * Tt * Dd + h * DHh;
    const int sub = tid >> 4, c4 = tid & 15;

    // ---- pass 1: norms only (shfl chains, iterations independent) ----
#pragma unroll
    for (int i = 0; i < 16; i++) {
        const int row = i * 8 + sub;
        const int t = pmeta[row] & 4095;
        float4 qv = *(const float4*)&Qb[(size_t)t * Dd + c4 * 4];
        float ss = qv.x * qv.x + qv.y * qv.y + qv.z * qv.z + qv.w * qv.w;
        ss += __shfl_xor_sync(0xffffffffu, ss, 1);
        ss += __shfl_xor_sync(0xffffffffu, ss, 2);
        ss += __shfl_xor_sync(0xffffffffu, ss, 4);
        ss += __shfl_xor_sync(0xffffffffu, ss, 8);
        if (c4 == 0) {
            const float nn = sqrtf(ss) + 1e-6f;
            rnorm[row] = 1.f / nn;
            if (row < 64) rsc[row] = nn;
        }
    }
    __syncthreads();

    // ---- pass 2: scale + split + store (no cross-lane deps, high MLP) ----
#pragma unroll
    for (int i = 0; i < 16; i++) {
        const int row = i * 8 + sub;
        const int t = pmeta[row] & 4095;
        const float rn = rnorm[row];
        float4 qv = *(const float4*)&Qb[(size_t)t * Dd + c4 * 4];
        const float a0 = qv.x * rn, a1 = qv.y * rn, a2 = qv.z * rn, a3 = qv.w * rn;
        __nv_bfloat162 kh01 = __floats2bfloat162_rn(a0, a1);
        __nv_bfloat162 kl01 = __floats2bfloat162_rn(a0 - __low2float(kh01), a1 - __high2float(kh01));
        __nv_bfloat162 kh23 = __floats2bfloat162_rn(a2, a3);
        __nv_bfloat162 kl23 = __floats2bfloat162_rn(a2 - __low2float(kh23), a3 - __high2float(kh23));
        *(__nv_bfloat162*)&kh_hi[row * KHP + c4 * 4]     = kh01;
        *(__nv_bfloat162*)&kh_hi[row * KHP + c4 * 4 + 2] = kh23;
        *(__nv_bfloat162*)&kh_lo[row * KHP + c4 * 4]     = kl01;
        *(__nv_bfloat162*)&kh_lo[row * KHP + c4 * 4 + 2] = kl23;

        float4 vv = *(const float4*)&Vb[(size_t)t * Dd + c4 * 4];
        __nv_bfloat162 vh01 = __floats2bfloat162_rn(vv.x, vv.y);
        __nv_bfloat162 vl01 = __floats2bfloat162_rn(vv.x - __low2float(vh01), vv.y - __high2float(vh01));
        __nv_bfloat162 vh23 = __floats2bfloat162_rn(vv.z, vv.w);
        __nv_bfloat162 vl23 = __floats2bfloat162_rn(vv.z - __low2float(vh23), vv.w - __high2float(vh23));
        *(__nv_bfloat162*)&v_hi[row * VP + c4 * 4]     = vh01;
        *(__nv_bfloat162*)&v_hi[row * VP + c4 * 4 + 2] = vh23;
        *(__nv_bfloat162*)&v_lo[row * VP + c4 * 4]     = vl01;
        *(__nv_bfloat162*)&v_lo[row * VP + c4 * 4 + 2] = vl23;
    }
    __syncthreads();

    const int w = tid >> 5, lane = tid & 31;
    const int g = lane >> 2, tg = lane & 3;
    const int i0 = w * 16;

    const uint32_t khb_hi = smem_u32(kh_hi), khb_lo = smem_u32(kh_lo);
    const uint32_t vb_hi  = smem_u32(v_hi),  vb_lo  = smem_u32(v_lo);
    const uint32_t aoff = ((i0 + (lane & 15)) * KHP + 8 * (lane >> 4)) * 2;
    const uint32_t boff = (((lane & 7) + ((lane >= 16) ? 8 : 0)) * KHP + ((lane >> 3) & 1) * 8) * 2;
    const uint32_t voff = (((lane & 7) + 8 * ((lane >> 3) & 1)) * VP + 8 * (lane >> 4)) * 2;

    // ---- dots: sweep-ordered MMAs (no back-to-back RAW on accumulators) ----
    float dc[16][4];
#pragma unroll
    for (int nt = 0; nt < 16; nt++)
#pragma unroll
        for (int k = 0; k < 4; k++) dc[nt][k] = 0.f;

#pragma unroll
    for (int k0 = 0; k0 < 64; k0 += 16) {
        uint32_t ah[4], al[4];
        LDSM4(ah[0], ah[1], ah[2], ah[3], khb_hi + aoff + k0 * 2);
        LDSM4(al[0], al[1], al[2], al[3], khb_lo + aoff + k0 * 2);
#pragma unroll
        for (int half = 0; half < 2; half++) {
            uint32_t bh[4][4], bl[4][4];
#pragma unroll
            for (int q = 0; q < 4; q++) {
                const int jt = half * 4 + q;
                const uint32_t jb = (uint32_t)(jt * 16 * KHP + k0) * 2;
                LDSM4(bh[q][0], bh[q][1], bh[q][2], bh[q][3], khb_hi + boff + jb);
                LDSM4(bl[q][0], bl[q][1], bl[q][2], bl[q][3], khb_lo + boff + jb);
            }
            // per-acc order preserved: hh, hl, lh
#pragma unroll
            for (int q = 0; q < 4; q++) {
                const int jt = half * 4 + q;
                MMA_BF16(dc[2 * jt],     ah, bh[q]);
                MMA_BF16(dc[2 * jt + 1], ah, bh[q] + 2);
            }
#pragma unroll
            for (int q = 0; q < 4; q++) {
                const int jt = half * 4 + q;
                MMA_BF16(dc[2 * jt],     ah, bl[q]);
                MMA_BF16(dc[2 * jt + 1], ah, bl[q] + 2);
            }
#pragma unroll
            for (int q = 0; q < 4; q++) {
                const int jt = half * 4 + q;
                MMA_BF16(dc[2 * jt],     al, bh[q]);
                MMA_BF16(dc[2 * jt + 1], al, bh[q] + 2);
            }
        }
    }

    // ---- masks + softmax in accumulator registers ----
    const int ra = i0 + g, rb = i0 + g + 8;
    {
        const int pka = pmeta[ra], pkb = pmeta[rb];
        const float sca = 0.125f * rsc[ra];
        const float scb = 0.125f * rsc[rb];

#pragma unroll
        for (int nt = 0; nt < 16; nt++) {
            const int j0 = nt * 8 + 2 * tg;
            const int pj0 = pmeta[j0], pj1 = pmeta[j0 + 1];
            float x;
            x = dc[nt][0] * sca;
            if ((pka >> 16) != (pj0 >> 16)) x = -1e9f;
            if (((pka ^ pj0) & 4095) == 0)  x = -1e-5f;
            dc[nt][0] = x;
            x = dc[nt][1] * sca;
            if ((pka >> 16) != (pj1 >> 16)) x = -1e9f;
            if (((pka ^ pj1) & 4095) == 0)  x = -1e-5f;
            dc[nt][1] = x;
            x = dc[nt][2] * scb;
            if ((pkb >> 16) != (pj0 >> 16)) x = -1e9f;
            if (((pkb ^ pj0) & 4095) == 0)  x = -1e-5f;
            dc[nt][2] = x;
            x = dc[nt][3] * scb;
            if ((pkb >> 16) != (pj1 >> 16)) x = -1e9f;
            if (((pkb ^ pj1) & 4095) == 0)  x = -1e-5f;
            dc[nt][3] = x;
        }

        float ma = -1e30f, mb = -1e30f;
#pragma unroll
        for (int nt = 0; nt < 16; nt++) {
            ma = fmaxf(ma, fmaxf(dc[nt][0], dc[nt][1]));
            mb = fmaxf(mb, fmaxf(dc[nt][2], dc[nt][3]));
        }
        ma = fmaxf(ma, __shfl_xor_sync(0xffffffffu, ma, 1));
        ma = fmaxf(ma, __shfl_xor_sync(0xffffffffu, ma, 2));
        mb = fmaxf(mb, __shfl_xor_sync(0xffffffffu, mb, 1));
        mb = fmaxf(mb, __shfl_xor_sync(0xffffffffu, mb, 2));

        float sa = 0.f, sb2 = 0.f;
#pragma unroll
        for (int nt = 0; nt < 16; nt++) {
            dc[nt][0] = __expf(dc[nt][0] - ma); sa  += dc[nt][0];
            dc[nt][1] = __expf(dc[nt][1] - ma); sa  += dc[nt][1];
            dc[nt][2] = __expf(dc[nt][2] - mb); sb2 += dc[nt][2];
            dc[nt][3] = __expf(dc[nt][3] - mb); sb2 += dc[nt][3];
        }
        sa  += __shfl_xor_sync(0xffffffffu, sa, 1);
        sa  += __shfl_xor_sync(0xffffffffu, sa, 2);
        sb2 += __shfl_xor_sync(0xffffffffu, sb2, 1);
        sb2 += __shfl_xor_sync(0xffffffffu, sb2, 2);

        if (tg == 0) {
            const int nhbase = ((int)n * Hh + h) * NHh;
            const int ta = pka & 4095, rra = (pka >> 12) & 3;
            const int tb = pkb & 4095, rrb = (pkb >> 12) & 3;
            g_logits[((size_t)nhbase + rra) * Tt + ta] = ma + __logf(sa);
            g_logits[((size_t)nhbase + rrb) * Tt + tb] = mb + __logf(sb2);
            invs[ra] = 1.f / sa;
            invs[rb] = 1.f / sb2;
        }
        __syncwarp();
    }

    // ---- PV: sweep-ordered, P fed straight from registers ----
    float oc[8][4];
#pragma unroll
    for (int nt = 0; nt < 8; nt++)
#pragma unroll
        for (int k = 0; k < 4; k++) oc[nt][k] = 0.f;

#pragma unroll
    for (int kc = 0; kc < 8; kc++) {
        uint32_t phi[4], plo[4];
        {
            __nv_bfloat162 hp, lp;
            hp = __floats2bfloat162_rn(dc[2 * kc][0], dc[2 * kc][1]);
            lp = __floats2bfloat162_rn(dc[2 * kc][0] - __low2float(hp),
                                       dc[2 * kc][1] - __high2float(hp));
            phi[0] = *(uint32_t*)&hp; plo[0] = *(uint32_t*)&lp;
            hp = __floats2bfloat162_rn(dc[2 * kc][2], dc[2 * kc][3]);
            lp = __floats2bfloat162_rn(dc[2 * kc][2] - __low2float(hp),
                                       dc[2 * kc][3] - __high2float(hp));
            phi[1] = *(uint32_t*)&hp; plo[1] = *(uint32_t*)&lp;
            hp = __floats2bfloat162_rn(dc[2 * kc + 1][0], dc[2 * kc + 1][1]);
            lp = __floats2bfloat162_rn(dc[2 * kc + 1][0] - __low2float(hp),
                                       dc[2 * kc + 1][1] - __high2float(hp));
            phi[2] = *(uint32_t*)&hp; plo[2] = *(uint32_t*)&lp;
            hp = __floats2bfloat162_rn(dc[2 * kc + 1][2], dc[2 * kc + 1][3]);
            lp = __floats2bfloat162_rn(dc[2 * kc + 1][2] - __low2float(hp),
                                       dc[2 * kc + 1][3] - __high2float(hp));
            phi[3] = *(uint32_t*)&hp; plo[3] = *(uint32_t*)&lp;
        }
        uint32_t vh[4][4], vl[4][4];
#pragma unroll
        for (int ft = 0; ft < 4; ft++) {
            const uint32_t vbo = (uint32_t)(kc * 16 * VP + ft * 16) * 2;
            LDSM4T(vh[ft][0], vh[ft][1], vh[ft][2], vh[ft][3], vb_hi + voff + vbo);
            LDSM4T(vl[ft][0], vl[ft][1], vl[ft][2], vl[ft][3], vb_lo + voff + vbo);
        }
        // per-acc order preserved: (phi,vh), (phi,vl), (plo,vh)
#pragma unroll
        for (int ft = 0; ft < 4; ft++) {
            MMA_BF16(oc[2 * ft],     phi, vh[ft]);
            MMA_BF16(oc[2 * ft + 1], phi, vh[ft] + 2);
        }
#pragma unroll
        for (int ft = 0; ft < 4; ft++) {
            MMA_BF16(oc[2 * ft],     phi, vl[ft]);
            MMA_BF16(oc[2 * ft + 1], phi, vl[ft] + 2);
        }
#pragma unroll
        for (int ft = 0; ft < 4; ft++) {
            MMA_BF16(oc[2 * ft],     plo, vh[ft]);
            MMA_BF16(oc[2 * ft + 1], plo, vh[ft] + 2);
        }
    }

    // ---- epilogue: scale by 1/s, scatter rows by pmeta ----
    {
        const int pka = pmeta[ra], pkb = pmeta[rb];
        const float iva = invs[ra], ivb = invs[rb];
        const size_t obase = ((size_t)n * Hh + h) * NHh;
        const size_t oa = ((obase + ((pka >> 12) & 3)) * Tt + (pka & 4095)) * DHh;
        const size_t ob = ((obase + ((pkb >> 12) & 3)) * Tt + (pkb & 4095)) * DHh;
#pragma unroll
        for (int ft = 0; ft < 4; ft++) {
            const int f0 = ft * 16 + 2 * tg;
            *(float2*)&g_O[oa + f0]     = make_float2(oc[2 * ft][0] * iva, oc[2 * ft][1] * iva);
            *(float2*)&g_O[ob + f0]     = make_float2(oc[2 * ft][2] * ivb, oc[2 * ft][3] * ivb);
            *(float2*)&g_O[oa + f0 + 8] = make_float2(oc[2 * ft + 1][0] * iva, oc[2 * ft + 1][1] * iva);
            *(float2*)&g_O[ob + f0 + 8] = make_float2(oc[2 * ft + 1][2] * ivb, oc[2 * ft + 1][3] * ivb);
        }
    }
}

// ================= round-combine softmax + LayerNorm ========================
__global__ void combine_ln_kernel(const float* __restrict__ gamma,
                                  const float* __restrict__ beta,
                                  float* __restrict__ out)
{
    const int bid = blockIdx.x;            // n*T + t
    const int n = bid >> 12, t = bid & 4095;
    const int tid = threadIdx.x;           // 128
    __shared__ float wsh[Hh][NHh];
    __shared__ float red[128];

    if (tid < Hh) {
        const int h = tid;
        float l[NHh];
        float m = -1e30f;
#pragma unroll
        for (int r = 0; r < NHh; r++) {
            l[r] = g_logits[(((size_t)n * Hh + h) * NHh + r) * Tt + t];
            m = fmaxf(m, l[r]);
        }
        float s = 0.f;
#pragma unroll
        for (int r = 0; r < NHh; r++) s += __expf(l[r] - m);
        const float lse = m + __logf(s);
#pragma unroll
        for (int r = 0; r < NHh; r++) wsh[h][r] = __expf(l[r] - lse);
    }
    __syncthreads();

    float vals[4];
    float lsum = 0.f, lsq = 0.f;
#pragma unroll
    for (int k2 = 0; k2 < 4; k2++) {
        const int d = tid + k2 * 128;
        const int h = d >> 6, f = d & 63;
        float a = 0.f;
#pragma unroll
        for (int r = 0; r < NHh; r++)
            a += wsh[h][r] * g_O[((((size_t)n * Hh + h) * NHh + r) * Tt + t) * DHh + f];
        vals[k2] = a;
        lsum += a;
        lsq  += a * a;
    }

    red[tid] = lsum;
    __syncthreads();
#pragma unroll
    for (int s = 64; s > 0; s >>= 1) {
        if (tid < s) red[tid] += red[tid + s];
        __syncthreads();
    }
    const float mu = red[0] * (1.f / Dd);
    __syncthreads();
    red[tid] = lsq;
    __syncthreads();
#pragma unroll
    for (int s = 64; s > 0; s >>= 1) {
        if (tid < s) red[tid] += red[tid + s];
        __syncthreads();
    }
    const float var = red[0] * (1.f / Dd) - mu * mu;
    const float rstd = rsqrtf(var + 1e-3f);

#pragma unroll
    for (int k2 = 0; k2 < 4; k2++) {
        const int d = tid + k2 * 128;
        out[(size_t)bid * Dd + d] = gamma[d] * (vals[k2] - mu) * rstd + beta[d];
    }
}

// ================= launch ===================================================
extern "C" void kernel_launch(void* const* d_in, const int* in_sizes, int n_in,
                              void* d_out, int out_size)
{
    const float* x     = (const float*)d_in[0];
    const float* W_Q   = (const float*)d_in[1];
    const float* b_Q   = (const float*)d_in[2];
    const float* W_V   = (const float*)d_in[3];
    const float* b_V   = (const float*)d_in[4];
    const float* gamma = (const float*)d_in[5];
    const float* beta  = (const float*)d_in[6];
    const float* rot   = (const float*)d_in[7];
    float* out = (float*)d_out;

    cudaFuncSetAttribute(attention_kernel,
                         cudaFuncAttributeMaxDynamicSharedMemorySize, SMEM_ATT3);
    cudaFuncSetAttribute(sort_kernel,
                         cudaFuncAttributeMaxDynamicSharedMemorySize, SMEM_SORT);
    cudaFuncSetAttribute(gemm_v_kernel,
                         cudaFuncAttributeMaxDynamicSharedMemorySize, SMEM_MMA);
    cudaFuncSetAttribute(bucket_kernel,
                         cudaFuncAttributeMaxDynamicSharedMemorySize, SMEM_BKT);

    split_w_kernel<<<dim3(16, 16), dim3(32, 8)>>>(W_V);

    dim3 qGrid(Dd / 128, (Nb * Tt) / 128);      // (4, 128)
    gemm_q_kernel<<<qGrid, 256>>>(x, W_Q, b_Q);

    dim3 vGrid(Dd / 128, (Nb * Tt) / 128);      // (4, 128)
    gemm_v_kernel<<<vGrid, 256, SMEM_MMA>>>(x, b_V);

    dim3 bGrid(Tt / 128, Hh, Nb);               // (32, 8, 4)
    bucket_kernel<<<bGrid, 256, SMEM_BKT>>>(rot);

    sort_kernel<<<Nb * Hh, 256, SMEM_SORT>>>(); // 32 blocks

    dim3 aGrid(CSs, Hh, Nb);                    // (256, 8, 4)
    attention_kernel<<<aGrid, 128, SMEM_ATT3>>>();

    combine_ln_kernel<<<Nb * Tt, 128>>>(gamma, beta, out);
}

// round 9
// speedup vs baseline: 1.0428x; 1.0428x over previous
#include <cuda_runtime.h>
#include <cuda_bf16.h>
#include <math.h>
#include <stdint.h>

// Problem constants
#define Nb   4          // batch
#define Tt   4096       // sequence length
#define Dd   512        // model dim
#define Hh   8          // heads
#define NHh  4          // hash rounds
#define BSs  64         // bucket chunk size
#define DHh  64         // head dim
#define NBb  64         // n_buckets
#define CSs  256        // chunks = NH * NB
#define Ll   16384      // NH * T

typedef unsigned long long u64;

// ---------------- scratch (device globals; no allocation allowed) ----------
__device__ float g_Q[(size_t)Nb * Tt * Dd];                 // 33.5 MB
__device__ float g_V[(size_t)Nb * Tt * Dd];                 // 33.5 MB
__device__ int   g_buckets[(size_t)Nb * Hh * NHh * Tt];     // 2 MB
__device__ int   g_perm[(size_t)Nb * Hh * Ll];              // 2 MB
__device__ float g_O[(size_t)Nb * Hh * NHh * Tt * DHh];     // 134 MB
__device__ float g_logits[(size_t)Nb * Hh * NHh * Tt];      // 2 MB
__device__ __nv_bfloat16 g_wthi[Dd * Dd];                   // 0.5 MB (W_V^T hi)
__device__ __nv_bfloat16 g_wtlo[Dd * Dd];                   // 0.5 MB (W_V^T lo)

// ================= helpers ==================================================
__device__ __forceinline__ uint32_t smem_u32(const void* p) {
    uint32_t a;
    asm("{ .reg .u64 t; cvta.to.shared.u64 t, %1; cvt.u32.u64 %0, t; }" : "=r"(a) : "l"(p));
    return a;
}
#define MMA_BF16(d, a, b)                                                     \
    asm volatile("mma.sync.aligned.m16n8k16.row.col.f32.bf16.bf16.f32 "       \
        "{%0,%1,%2,%3}, {%4,%5,%6,%7}, {%8,%9}, {%0,%1,%2,%3};"               \
        : "+f"((d)[0]), "+f"((d)[1]), "+f"((d)[2]), "+f"((d)[3])              \
        : "r"((a)[0]), "r"((a)[1]), "r"((a)[2]), "r"((a)[3]),                 \
          "r"((b)[0]), "r"((b)[1]))
#define LDSM4(r0, r1, r2, r3, addr)                                           \
    asm volatile("ldmatrix.sync.aligned.m8n8.x4.shared.b16 {%0,%1,%2,%3}, [%4];" \
        : "=r"(r0), "=r"(r1), "=r"(r2), "=r"(r3) : "r"(addr))
#define LDSM4T(r0, r1, r2, r3, addr)                                          \
    asm volatile("ldmatrix.sync.aligned.m8n8.x4.trans.shared.b16 {%0,%1,%2,%3}, [%4];" \
        : "=r"(r0), "=r"(r1), "=r"(r2), "=r"(r3) : "r"(addr))

// packed dual-fp32 FMA (sm_100+): two independent exact fp32 FMAs per instr
#define FFMA2(d, a, b) \
    asm("fma.rn.f32x2 %0, %1, %2, %0;" : "+l"(d) : "l"(a), "l"(b))
#define PACK2(d, x, y) \
    asm("mov.b64 %0, {%1, %2};" : "=l"(d) : "f"(x), "f"(y))
#define UNPACK2(x, y, d) \
    asm("mov.b64 {%0, %1}, %2;" : "=f"(x), "=f"(y) : "l"(d))

// ================= Q GEMM: fp32 SIMT + FFMA2 (exact path) ===================
__global__ __launch_bounds__(256, 2)
void gemm_q_kernel(const float* __restrict__ A,
                   const float* __restrict__ W, const float* __restrict__ bias)
{
    __shared__ float As[16][132];
    __shared__ float Bs[16][132];

    const int tid = threadIdx.x;
    const int tx = tid & 15, ty = tid >> 4;
    const int rowBase = blockIdx.y * 128;
    const int colBase = blockIdx.x * 128;

    u64 acc2[8][4];
#pragma unroll
    for (int i = 0; i < 8; i++)
#pragma unroll
        for (int j = 0; j < 4; j++) acc2[i][j] = 0ull;

    for (int kt = 0; kt < Dd; kt += 16) {
#pragma unroll
        for (int l = 0; l < 2; l++) {
            int e = tid + l * 256;
            int r = e >> 2, c4 = e & 3;
            float4 v = *(const float4*)&A[(size_t)(rowBase + r) * Dd + kt + c4 * 4];
            As[c4 * 4 + 0][r] = v.x;
            As[c4 * 4 + 1][r] = v.y;
            As[c4 * 4 + 2][r] = v.z;
            As[c4 * 4 + 3][r] = v.w;
        }
#pragma unroll
        for (int l = 0; l < 2; l++) {
            int e = tid + l * 256;
            int r = e >> 5, c4 = e & 31;
            float4 v = *(const float4*)&W[(size_t)(kt + r) * Dd + colBase + c4 * 4];
            *(float4*)&Bs[r][c4 * 4] = v;
        }
        __syncthreads();
#pragma unroll
        for (int k = 0; k < 16; k++) {
            float a[8];
            *(float4*)&a[0] = *(const float4*)&As[k][ty * 8];
            *(float4*)&a[4] = *(const float4*)&As[k][ty * 8 + 4];
            u64 a2[8];
#pragma unroll
            for (int i = 0; i < 8; i++) PACK2(a2[i], a[i], a[i]);
            ulonglong2 bp0 = *(const ulonglong2*)&Bs[k][tx * 8];
            ulonglong2 bp1 = *(const ulonglong2*)&Bs[k][tx * 8 + 4];
            u64 b2[4] = {bp0.x, bp0.y, bp1.x, bp1.y};
#pragma unroll
            for (int i = 0; i < 8; i++)
#pragma unroll
                for (int j = 0; j < 4; j++) FFMA2(acc2[i][j], a2[i], b2[j]);
        }
        __syncthreads();
    }
#pragma unroll
    for (int i = 0; i < 8; i++) {
        const int row = rowBase + ty * 8 + i;
#pragma unroll
        for (int j4 = 0; j4 < 2; j4++) {
            const int col = colBase + tx * 8 + j4 * 4;
            float e0, e1, e2, e3;
            UNPACK2(e0, e1, acc2[i][j4 * 2]);
            UNPACK2(e2, e3, acc2[i][j4 * 2 + 1]);
            float4 o;
            o.x = e0 + bias[col + 0];
            o.y = e1 + bias[col + 1];
            o.z = e2 + bias[col + 2];
            o.w = e3 + bias[col + 3];
            *(float4*)&g_Q[(size_t)row * Dd + col] = o;
        }
    }
}

// ================= split + transpose W_V ====================================
__global__ void split_w_kernel(const float* __restrict__ W)
{
    __shared__ float tile[32][33];
    const int bx = blockIdx.x * 32;   // n block
    const int by = blockIdx.y * 32;   // k block
    const int tx = threadIdx.x, ty = threadIdx.y;   // 32 x 8
#pragma unroll
    for (int r = 0; r < 32; r += 8)
        tile[ty + r][tx] = W[(size_t)(by + ty + r) * Dd + bx + tx];
    __syncthreads();
#pragma unroll
    for (int r = 0; r < 32; r += 8) {
        float val = tile[tx][ty + r];
        __nv_bfloat16 hi = __float2bfloat16(val);
        __nv_bfloat16 lo = __float2bfloat16(val - __bfloat162float(hi));
        size_t o = (size_t)(bx + ty + r) * Dd + by + tx;
        g_wthi[o] = hi;
        g_wtlo[o] = lo;
    }
}

// ================= V GEMM: mma.sync bf16 3-term (R7 proven version) =========
#define PITCH 40
#define A_HI  0
#define A_LO  (128 * PITCH)
#define B_HI  (2 * 128 * PITCH)
#define B_LO  (2 * 128 * PITCH + 256 * PITCH)
#define SMEM_MMA ((2 * 128 * PITCH + 2 * 256 * PITCH) * 2)

__global__ __launch_bounds__(512, 1)
void gemm_v_kernel(const float* __restrict__ x, const float* __restrict__ bias)
{
    extern __shared__ uint16_t sm16[];
    const int tid = threadIdx.x;
    const int wid = tid >> 5, lane = tid & 31;
    const int g = lane >> 2, tg = lane & 3;
    const int wm = wid & 3, wn = wid >> 2;
    const int mbase = blockIdx.y * 128;
    const int ncol0 = blockIdx.x * 256;

    float acc[2][8][4];
#pragma unroll
    for (int i = 0; i < 2; i++)
#pragma unroll
        for (int j = 0; j < 8; j++)
#pragma unroll
            for (int k = 0; k < 4; k++) acc[i][j][k] = 0.f;

    for (int slab = 0; slab < 16; slab++) {
        const int kt = slab * 32;
#pragma unroll
        for (int i = 0; i < 2; i++) {
            const int e = tid + i * 512;
            const int m = e >> 3, k4 = e & 7;
            float4 v = *(const float4*)&x[(size_t)(mbase + m) * Dd + kt + k4 * 4];
            __nv_bfloat162 h01 = __floats2bfloat162_rn(v.x, v.y);
            __nv_bfloat162 h23 = __floats2bfloat162_rn(v.z, v.w);
            __nv_bfloat162 l01 = __floats2bfloat162_rn(v.x - __low2float(h01),
                                                       v.y - __high2float(h01));
            __nv_bfloat162 l23 = __floats2bfloat162_rn(v.z - __low2float(h23),
                                                       v.w - __high2float(h23));
            const int off = m * PITCH + k4 * 4;
            *(__nv_bfloat162*)(sm16 + A_HI + off)     = h01;
            *(__nv_bfloat162*)(sm16 + A_HI + off + 2) = h23;
            *(__nv_bfloat162*)(sm16 + A_LO + off)     = l01;
            *(__nv_bfloat162*)(sm16 + A_LO + off + 2) = l23;
        }
#pragma unroll
        for (int i = 0; i < 4; i++) {
            const int e = tid + i * 512;
            const int split = e >> 10;
            const int r = (e >> 2) & 255;
            const int k8 = e & 3;
            const __nv_bfloat16* src = (split ? g_wtlo : g_wthi)
                + (size_t)(ncol0 + r) * Dd + kt + k8 * 8;
            *(uint4*)(sm16 + (split ? B_LO : B_HI) + r * PITCH + k8 * 8)
                = *(const uint4*)src;
        }
        __syncthreads();

#pragma unroll
        for (int kk = 0; kk < 32; kk += 16) {
            uint32_t ah[2][4], al[2][4];
#pragma unroll
            for (int mt = 0; mt < 2; mt++) {
                const int ro = (wm * 32 + mt * 16 + g) * PITCH + kk + 2 * tg;
                ah[mt][0] = *(const uint32_t*)(sm16 + A_HI + ro);
                ah[mt][1] = *(const uint32_t*)(sm16 + A_HI + ro + 8 * PITCH);
                ah[mt][2] = *(const uint32_t*)(sm16 + A_HI + ro + 8);
                ah[mt][3] = *(const uint32_t*)(sm16 + A_HI + ro + 8 * PITCH + 8);
                al[mt][0] = *(const uint32_t*)(sm16 + A_LO + ro);
                al[mt][1] = *(const uint32_t*)(sm16 + A_LO + ro + 8 * PITCH);
                al[mt][2] = *(const uint32_t*)(sm16 + A_LO + ro + 8);
                al[mt][3] = *(const uint32_t*)(sm16 + A_LO + ro + 8 * PITCH + 8);
            }
#pragma unroll
            for (int ng = 0; ng < 2; ng++) {
                uint32_t bh[4][2], bl[4][2];
#pragma unroll
                for (int q = 0; q < 4; q++) {
                    const int ro = (wn * 64 + (ng * 4 + q) * 8 + g) * PITCH + kk + 2 * tg;
                    bh[q][0] = *(const uint32_t*)(sm16 + B_HI + ro);
                    bh[q][1] = *(const uint32_t*)(sm16 + B_HI + ro + 8);
                    bl[q][0] = *(const uint32_t*)(sm16 + B_LO + ro);
                    bl[q][1] = *(const uint32_t*)(sm16 + B_LO + ro + 8);
                }
#pragma unroll
                for (int mt = 0; mt < 2; mt++)
#pragma unroll
                    for (int q = 0; q < 4; q++) {
                        float* d = acc[mt][ng * 4 + q];
                        MMA_BF16(d, ah[mt], bh[q]);
                        MMA_BF16(d, ah[mt], bl[q]);
                        MMA_BF16(d, al[mt], bh[q]);
                    }
            }
        }
        __syncthreads();
    }

#pragma unroll
    for (int mt = 0; mt < 2; mt++) {
        const int r0 = mbase + wm * 32 + mt * 16 + g;
#pragma unroll
        for (int nt = 0; nt < 8; nt++) {
            const int col = ncol0 + wn * 64 + nt * 8 + 2 * tg;
            float2 b2 = *(const float2*)&bias[col];
            float2 o0, o1;
            o0.x = acc[mt][nt][0] + b2.x;
            o0.y = acc[mt][nt][1] + b2.y;
            o1.x = acc[mt][nt][2] + b2.x;
            o1.y = acc[mt][nt][3] + b2.y;
            *(float2*)&g_V[(size_t)r0 * Dd + col] = o0;
            *(float2*)&g_V[(size_t)(r0 + 8) * Dd + col] = o1;
        }
    }
}

// ================= bucket kernel: rotation GEMM (FFMA2) + fused argmax ======
#define AsP 68
#define BsP 132
#define SMEM_BKT ((128 * AsP + 64 * BsP) * 4)

__global__ __launch_bounds__(256, 2)
void bucket_kernel(const float* __restrict__ rot)
{
    extern __shared__ float smf[];
    float* As = smf;                  // [128 m][68 k]
    float* Bs = smf + 128 * AsP;      // [64 k][132 c]

    const int h = blockIdx.y, n = blockIdx.z;
    const int tid = threadIdx.x;      // 256
    const int tx = tid & 15, ty = tid >> 4;
    const int t0 = blockIdx.x * 128;

    const float* Qb = g_Q + ((size_t)n * Tt + t0) * Dd + h * DHh;
#pragma unroll
    for (int l = 0; l < 8; l++) {
        const int e = tid + l * 256;
        const int r = e >> 4, c4 = e & 15;
        *(float4*)&As[r * AsP + c4 * 4] = *(const float4*)&Qb[(size_t)r * Dd + c4 * 4];
    }
    const float* Rb = rot + (size_t)h * 8192;
#pragma unroll
    for (int l = 0; l < 8; l++) {
        const int e = tid + l * 256;
        const int kr = e >> 5, c4 = e & 31;
        *(float4*)&Bs[kr * BsP + c4 * 4] = *(const float4*)&Rb[kr * 128 + c4 * 4];
    }
    __syncthreads();

    u64 acc2[8][4];
#pragma unroll
    for (int i = 0; i < 8; i++)
#pragma unroll
        for (int j = 0; j < 4; j++) acc2[i][j] = 0ull;

#pragma unroll 4
    for (int k = 0; k < 64; k++) {
        float a[8];
#pragma unroll
        for (int i = 0; i < 8; i++) a[i] = As[(ty * 8 + i) * AsP + k];
        u64 a2[8];
#pragma unroll
        for (int i = 0; i < 8; i++) PACK2(a2[i], a[i], a[i]);
        ulonglong2 bp0 = *(const ulonglong2*)&Bs[k * BsP + tx * 8];
        ulonglong2 bp1 = *(const ulonglong2*)&Bs[k * BsP + tx * 8 + 4];
        u64 b2[4] = {bp0.x, bp0.y, bp1.x, bp1.y};
#pragma unroll
        for (int i = 0; i < 8; i++)
#pragma unroll
            for (int j = 0; j < 4; j++) FFMA2(acc2[i][j], a2[i], b2[j]);
    }

    const int ig = (tx & 3) * 8;
    const int r = tx >> 2;
#pragma unroll
    for (int i = 0; i < 8; i++) {
        float acc[8];
#pragma unroll
        for (int jp = 0; jp < 4; jp++)
            UNPACK2(acc[2 * jp], acc[2 * jp + 1], acc2[i][jp]);

        float bv = acc[0];
        int bidx = ig;
#pragma unroll
        for (int j = 1; j < 8; j++)
            if (acc[j] > bv) { bv = acc[j]; bidx = ig + j; }
#pragma unroll
        for (int j = 0; j < 8; j++)
            if (-acc[j] > bv) { bv = -acc[j]; bidx = 32 + ig + j; }

        float ov; int oi;
        ov = __shfl_xor_sync(0xffffffffu, bv, 1);
        oi = __shfl_xor_sync(0xffffffffu, bidx, 1);
        if (ov > bv || (ov == bv && oi < bidx)) { bv = ov; bidx = oi; }
        ov = __shfl_xor_sync(0xffffffffu, bv, 2);
        oi = __shfl_xor_sync(0xffffffffu, bidx, 2);
        if (ov > bv || (ov == bv && oi < bidx)) { bv = ov; bidx = oi; }

        if ((tx & 3) == 0)
            g_buckets[(((size_t)n * Hh + h) * NHh + r) * Tt + t0 + ty * 8 + i]
                = bidx + r * NBb;
    }
}

// ================= segmented stable counting sort per (n,h) =================
#define HROW 258
#define SMEM_SORT (Ll + 256 * HROW * 2 + 256 * 4)
__global__ void sort_kernel()
{
    extern __shared__ char smraw[];
    unsigned char*  sb   = (unsigned char*)smraw;
    unsigned short* hist = (unsigned short*)(smraw + Ll);
    int*            base = (int*)(smraw + Ll + 256 * HROW * 2);
    __shared__ int tot[256];

    const int nh = blockIdx.x;
    const int tid = threadIdx.x;

    for (int e = tid; e < 256 * HROW / 2; e += 256)
        ((unsigned int*)hist)[e] = 0;
    __syncthreads();

    const int* bptr = g_buckets + (size_t)nh * Ll;
    for (int e = tid; e < Ll; e += 256)
        sb[e] = (unsigned char)bptr[e];
    __syncthreads();

    {
        const int s = tid;
#pragma unroll 4
        for (int j = 0; j < 64; j++) {
            int b = sb[s * 64 + j];
            hist[b * HROW + s]++;
        }
    }
    __syncthreads();

    {
        const unsigned short* row = &hist[tid * HROW];
        int sum = 0;
#pragma unroll 8
        for (int s2 = 0; s2 < 256; s2++) sum += row[s2];
        tot[tid] = sum;
    }
    __syncthreads();
    if (tid == 0) {
        int run = 0;
        for (int b = 0; b < 256; b++) { base[b] = run; run += tot[b]; }
    }
    __syncthreads();

    {
        unsigned short* row = &hist[tid * HROW];
        unsigned short run = 0;
        for (int s2 = 0; s2 < 256; s2++) {
            unsigned short v = row[s2];
            row[s2] = run;
            run = (unsigned short)(run + v);
        }
    }
    __syncthreads();

    {
        const int s = tid;
        int* pout = g_perm + (size_t)nh * Ll;
        for (int j = 0; j < 64; j++) {
            int i = s * 64 + j;
            int b = sb[i];
            unsigned short off = hist[b * HROW + s];
            hist[b * HROW + s] = (unsigned short)(off + 1);
            pout[base[b] + off] = (b << 16) | i;
        }
    }
}

// ================= chunked attention (R7 proven version) ====================
#define KHP 72
#define VP  72
#define OKH_HI 0
#define OKH_LO 18432
#define OV_HI  36864
#define OV_LO  55296
#define OMETA  73728
#define ORSC   74240
#define OINVS  74496
#define SMEM_ATT3 74752

__global__ __launch_bounds__(128, 3)
void attention_kernel()
{
    extern __shared__ char smb[];
    __nv_bfloat16* kh_hi = (__nv_bfloat16*)(smb + OKH_HI);   // [128][72]
    __nv_bfloat16* kh_lo = (__nv_bfloat16*)(smb + OKH_LO);
    __nv_bfloat16* v_hi  = (__nv_bfloat16*)(smb + OV_HI);    // [128][72]
    __nv_bfloat16* v_lo  = (__nv_bfloat16*)(smb + OV_LO);
    int*   pmeta = (int*)(smb + OMETA);                      // 128
    float* rsc   = (float*)(smb + ORSC);                     // 64
    float* invs  = (float*)(smb + OINVS);                    // 64

    const int c = blockIdx.x, h = blockIdx.y, n = blockIdx.z;
    const int tid = threadIdx.x;
    const int pc = (c + CSs - 1) % CSs;

    {
        const int p = (tid < 64) ? (c * BSs + tid) : (pc * BSs + (tid - 64));
        pmeta[tid] = g_perm[((size_t)n * Hh + h) * Ll + p];
    }
    __syncthreads();

    const float* Qb = g_Q + (size_t)n * Tt * Dd + h * DHh;
    const float* Vb = g_V + (size_t)n * Tt * Dd + h * DHh;
    const int sub = tid >> 4, c4 = tid & 15;
#pragma unroll
    for (int i = 0; i < 16; i++) {
        const int row = i * 8 + sub;
        const int t = pmeta[row] & 4095;
        float4 qv = *(const float4*)&Qb[(size_t)t * Dd + c4 * 4];
        float ss = qv.x * qv.x + qv.y * qv.y + qv.z * qv.z + qv.w * qv.w;
        ss += __shfl_xor_sync(0xffffffffu, ss, 1);
        ss += __shfl_xor_sync(0xffffffffu, ss, 2);
        ss += __shfl_xor_sync(0xffffffffu, ss, 4);
        ss += __shfl_xor_sync(0xffffffffu, ss, 8);
        const float nn = sqrtf(ss) + 1e-6f;
        const float rn = 1.f / nn;
        if (c4 == 0 && row < 64) rsc[row] = nn;

        const float a0 = qv.x * rn, a1 = qv.y * rn, a2 = qv.z * rn, a3 = qv.w * rn;
        __nv_bfloat162 kh01 = __floats2bfloat162_rn(a0, a1);
        __nv_bfloat162 kl01 = __floats2bfloat162_rn(a0 - __low2float(kh01), a1 - __high2float(kh01));
        __nv_bfloat162 kh23 = __floats2bfloat162_rn(a2, a3);
        __nv_bfloat162 kl23 = __floats2bfloat162_rn(a2 - __low2float(kh23), a3 - __high2float(kh23));
        *(__nv_bfloat162*)&kh_hi[row * KHP + c4 * 4]     = kh01;
        *(__nv_bfloat162*)&kh_hi[row * KHP + c4 * 4 + 2] = kh23;
        *(__nv_bfloat162*)&kh_lo[row * KHP + c4 * 4]     = kl01;
        *(__nv_bfloat162*)&kh_lo[row * KHP + c4 * 4 + 2] = kl23;

        float4 vv = *(const float4*)&Vb[(size_t)t * Dd + c4 * 4];
        __nv_bfloat162 vh01 = __floats2bfloat162_rn(vv.x, vv.y);
        __nv_bfloat162 vl01 = __floats2bfloat162_rn(vv.x - __low2float(vh01), vv.y - __high2float(vh01));
        __nv_bfloat162 vh23 = __floats2bfloat162_rn(vv.z, vv.w);
        __nv_bfloat162 vl23 = __floats2bfloat162_rn(vv.z - __low2float(vh23), vv.w - __high2float(vh23));
        *(__nv_bfloat162*)&v_hi[row * VP + c4 * 4]     = vh01;
        *(__nv_bfloat162*)&v_hi[row * VP + c4 * 4 + 2] = vh23;
        *(__nv_bfloat162*)&v_lo[row * VP + c4 * 4]     = vl01;
        *(__nv_bfloat162*)&v_lo[row * VP + c4 * 4 + 2] = vl23;
    }
    __syncthreads();

    const int w = tid >> 5, lane = tid & 31;
    const int g = lane >> 2, tg = lane & 3;
    const int i0 = w * 16;

    const uint32_t khb_hi = smem_u32(kh_hi), khb_lo = smem_u32(kh_lo);
    const uint32_t vb_hi  = smem_u32(v_hi),  vb_lo  = smem_u32(v_lo);
    const uint32_t aoff = ((i0 + (lane & 15)) * KHP + 8 * (lane >> 4)) * 2;
    const uint32_t boff = (((lane & 7) + ((lane >= 16) ? 8 : 0)) * KHP + ((lane >> 3) & 1) * 8) * 2;
    const uint32_t voff = (((lane & 7) + 8 * ((lane >> 3) & 1)) * VP + 8 * (lane >> 4)) * 2;

    // ---- dots: warp w computes S rows i0..i0+15 over all 128 j ----
    float dc[16][4];
#pragma unroll
    for (int nt = 0; nt < 16; nt++)
#pragma unroll
        for (int k = 0; k < 4; k++) dc[nt][k] = 0.f;

#pragma unroll
    for (int k0 = 0; k0 < 64; k0 += 16) {
        uint32_t ah[4], al[4];
        LDSM4(ah[0], ah[1], ah[2], ah[3], khb_hi + aoff + k0 * 2);
        LDSM4(al[0], al[1], al[2], al[3], khb_lo + aoff + k0 * 2);
#pragma unroll
        for (int jt = 0; jt < 8; jt++) {
            uint32_t bh[4], bl[4];
            const uint32_t jb = (uint32_t)(jt * 16 * KHP + k0) * 2;
            LDSM4(bh[0], bh[1], bh[2], bh[3], khb_hi + boff + jb);
            LDSM4(bl[0], bl[1], bl[2], bl[3], khb_lo + boff + jb);
            MMA_BF16(dc[2 * jt], ah, bh);
            MMA_BF16(dc[2 * jt], ah, bl);
            MMA_BF16(dc[2 * jt], al, bh);
            MMA_BF16(dc[2 * jt + 1], ah, bh + 2);
            MMA_BF16(dc[2 * jt + 1], ah, bl + 2);
            MMA_BF16(dc[2 * jt + 1], al, bh + 2);
        }
    }

    // ---- masks + softmax in accumulator registers ----
    const int ra = i0 + g, rb = i0 + g + 8;
    {
        const int pka = pmeta[ra], pkb = pmeta[rb];
        const float sca = 0.125f * rsc[ra];
        const float scb = 0.125f * rsc[rb];

#pragma unroll
        for (int nt = 0; nt < 16; nt++) {
            const int j0 = nt * 8 + 2 * tg;
            const int pj0 = pmeta[j0], pj1 = pmeta[j0 + 1];
            float x;
            x = dc[nt][0] * sca;
            if ((pka >> 16) != (pj0 >> 16)) x = -1e9f;
            if (((pka ^ pj0) & 4095) == 0)  x = -1e-5f;
            dc[nt][0] = x;
            x = dc[nt][1] * sca;
            if ((pka >> 16) != (pj1 >> 16)) x = -1e9f;
            if (((pka ^ pj1) & 4095) == 0)  x = -1e-5f;
            dc[nt][1] = x;
            x = dc[nt][2] * scb;
            if ((pkb >> 16) != (pj0 >> 16)) x = -1e9f;
            if (((pkb ^ pj0) & 4095) == 0)  x = -1e-5f;
            dc[nt][2] = x;
            x = dc[nt][3] * scb;
            if ((pkb >> 16) != (pj1 >> 16)) x = -1e9f;
            if (((pkb ^ pj1) & 4095) == 0)  x = -1e-5f;
            dc[nt][3] = x;
        }

        float ma = -1e30f, mb = -1e30f;
#pragma unroll
        for (int nt = 0; nt < 16; nt++) {
            ma = fmaxf(ma, fmaxf(dc[nt][0], dc[nt][1]));
            mb = fmaxf(mb, fmaxf(dc[nt][2], dc[nt][3]));
        }
        ma = fmaxf(ma, __shfl_xor_sync(0xffffffffu, ma, 1));
        ma = fmaxf(ma, __shfl_xor_sync(0xffffffffu, ma, 2));
        mb = fmaxf(mb, __shfl_xor_sync(0xffffffffu, mb, 1));
        mb = fmaxf(mb, __shfl_xor_sync(0xffffffffu, mb, 2));

        float sa = 0.f, sb2 = 0.f;
#pragma unroll
        for (int nt = 0; nt < 16; nt++) {
            dc[nt][0] = __expf(dc[nt][0] - ma); sa  += dc[nt][0];
            dc[nt][1] = __expf(dc[nt][1] - ma); sa  += dc[nt][1];
            dc[nt][2] = __expf(dc[nt][2] - mb); sb2 += dc[nt][2];
            dc[nt][3] = __expf(dc[nt][3] - mb); sb2 += dc[nt][3];
        }
        sa  += __shfl_xor_sync(0xffffffffu, sa, 1);
        sa  += __shfl_xor_sync(0xffffffffu, sa, 2);
        sb2 += __shfl_xor_sync(0xffffffffu, sb2, 1);
        sb2 += __shfl_xor_sync(0xffffffffu, sb2, 2);

        if (tg == 0) {
            const int nhbase = ((int)n * Hh + h) * NHh;
            const int ta = pka & 4095, rra = (pka >> 12) & 3;
            const int tb = pkb & 4095, rrb = (pkb >> 12) & 3;
            g_logits[((size_t)nhbase + rra) * Tt + ta] = ma + __logf(sa);
            g_logits[((size_t)nhbase + rrb) * Tt + tb] = mb + __logf(sb2);
            invs[ra] = 1.f / sa;
            invs[rb] = 1.f / sb2;
        }
        __syncwarp();
    }

    // ---- PV: O[i0..15][0..63] = P @ V ; P fed straight from registers ----
    float oc[8][4];
#pragma unroll
    for (int nt = 0; nt < 8; nt++)
#pragma unroll
        for (int k = 0; k < 4; k++) oc[nt][k] = 0.f;

#pragma unroll
    for (int kc = 0; kc < 8; kc++) {
        uint32_t phi[4], plo[4];
        {
            __nv_bfloat162 hp, lp;
            hp = __floats2bfloat162_rn(dc[2 * kc][0], dc[2 * kc][1]);
            lp = __floats2bfloat162_rn(dc[2 * kc][0] - __low2float(hp),
                                       dc[2 * kc][1] - __high2float(hp));
            phi[0] = *(uint32_t*)&hp; plo[0] = *(uint32_t*)&lp;
            hp = __floats2bfloat162_rn(dc[2 * kc][2], dc[2 * kc][3]);
            lp = __floats2bfloat162_rn(dc[2 * kc][2] - __low2float(hp),
                                       dc[2 * kc][3] - __high2float(hp));
            phi[1] = *(uint32_t*)&hp; plo[1] = *(uint32_t*)&lp;
            hp = __floats2bfloat162_rn(dc[2 * kc + 1][0], dc[2 * kc + 1][1]);
            lp = __floats2bfloat162_rn(dc[2 * kc + 1][0] - __low2float(hp),
                                       dc[2 * kc + 1][1] - __high2float(hp));
            phi[2] = *(uint32_t*)&hp; plo[2] = *(uint32_t*)&lp;
            hp = __floats2bfloat162_rn(dc[2 * kc + 1][2], dc[2 * kc + 1][3]);
            lp = __floats2bfloat162_rn(dc[2 * kc + 1][2] - __low2float(hp),
                                       dc[2 * kc + 1][3] - __high2float(hp));
            phi[3] = *(uint32_t*)&hp; plo[3] = *(uint32_t*)&lp;
        }
#pragma unroll
        for (int ft = 0; ft < 4; ft++) {
            uint32_t vh[4], vl[4];
            const uint32_t vbo = (uint32_t)(kc * 16 * VP + ft * 16) * 2;
            LDSM4T(vh[0], vh[1], vh[2], vh[3], vb_hi + voff + vbo);
            LDSM4T(vl[0], vl[1], vl[2], vl[3], vb_lo + voff + vbo);
            MMA_BF16(oc[2 * ft], phi, vh);
            MMA_BF16(oc[2 * ft], phi, vl);
            MMA_BF16(oc[2 * ft], plo, vh);
            MMA_BF16(oc[2 * ft + 1], phi, vh + 2);
            MMA_BF16(oc[2 * ft + 1], phi, vl + 2);
            MMA_BF16(oc[2 * ft + 1], plo, vh + 2);
        }
    }

    // ---- epilogue: scale by 1/s, scatter rows by pmeta ----
    {
        const int pka = pmeta[ra], pkb = pmeta[rb];
        const float iva = invs[ra], ivb = invs[rb];
        const size_t obase = ((size_t)n * Hh + h) * NHh;
        const size_t oa = ((obase + ((pka >> 12) & 3)) * Tt + (pka & 4095)) * DHh;
        const size_t ob = ((obase + ((pkb >> 12) & 3)) * Tt + (pkb & 4095)) * DHh;
#pragma unroll
        for (int ft = 0; ft < 4; ft++) {
            const int f0 = ft * 16 + 2 * tg;
            *(float2*)&g_O[oa + f0]     = make_float2(oc[2 * ft][0] * iva, oc[2 * ft][1] * iva);
            *(float2*)&g_O[ob + f0]     = make_float2(oc[2 * ft][2] * ivb, oc[2 * ft][3] * ivb);
            *(float2*)&g_O[oa + f0 + 8] = make_float2(oc[2 * ft + 1][0] * iva, oc[2 * ft + 1][1] * iva);
            *(float2*)&g_O[ob + f0 + 8] = make_float2(oc[2 * ft + 1][2] * ivb, oc[2 * ft + 1][3] * ivb);
        }
    }
}

// ================= round-combine softmax + LayerNorm ========================
__global__ void combine_ln_kernel(const float* __restrict__ gamma,
                                  const float* __restrict__ beta,
                                  float* __restrict__ out)
{
    const int bid = blockIdx.x;            // n*T + t
    const int n = bid >> 12, t = bid & 4095;
    const int tid = threadIdx.x;           // 128
    __shared__ float wsh[Hh][NHh];
    __shared__ float red[128];

    if (tid < Hh) {
        const int h = tid;
        float l[NHh];
        float m = -1e30f;
#pragma unroll
        for (int r = 0; r < NHh; r++) {
            l[r] = g_logits[(((size_t)n * Hh + h) * NHh + r) * Tt + t];
            m = fmaxf(m, l[r]);
        }
        float s = 0.f;
#pragma unroll
        for (int r = 0; r < NHh; r++) s += __expf(l[r] - m);
        const float lse = m + __logf(s);
#pragma unroll
        for (int r = 0; r < NHh; r++) wsh[h][r] = __expf(l[r] - lse);
    }
    __syncthreads();

    float vals[4];
    float lsum = 0.f, lsq = 0.f;
#pragma unroll
    for (int k2 = 0; k2 < 4; k2++) {
        const int d = tid + k2 * 128;
        const int h = d >> 6, f = d & 63;
        float a = 0.f;
#pragma unroll
        for (int r = 0; r < NHh; r++)
            a += wsh[h][r] * g_O[((((size_t)n * Hh + h) * NHh + r) * Tt + t) * DHh + f];
        vals[k2] = a;
        lsum += a;
        lsq  += a * a;
    }

    red[tid] = lsum;
    __syncthreads();
#pragma unroll
    for (int s = 64; s > 0; s >>= 1) {
        if (tid < s) red[tid] += red[tid + s];
        __syncthreads();
    }
    const float mu = red[0] * (1.f / Dd);
    __syncthreads();
    red[tid] = lsq;
    __syncthreads();
#pragma unroll
    for (int s = 64; s > 0; s >>= 1) {
        if (tid < s) red[tid] += red[tid + s];
        __syncthreads();
    }
    const float var = red[0] * (1.f / Dd) - mu * mu;
    const float rstd = rsqrtf(var + 1e-3f);

#pragma unroll
    for (int k2 = 0; k2 < 4; k2++) {
        const int d = tid + k2 * 128;
        out[(size_t)bid * Dd + d] = gamma[d] * (vals[k2] - mu) * rstd + beta[d];
    }
}

// ================= launch ===================================================
extern "C" void kernel_launch(void* const* d_in, const int* in_sizes, int n_in,
                              void* d_out, int out_size)
{
    const float* x     = (const float*)d_in[0];
    const float* W_Q   = (const float*)d_in[1];
    const float* b_Q   = (const float*)d_in[2];
    const float* W_V   = (const float*)d_in[3];
    const float* b_V   = (const float*)d_in[4];
    const float* gamma = (const float*)d_in[5];
    const float* beta  = (const float*)d_in[6];
    const float* rot   = (const float*)d_in[7];
    float* out = (float*)d_out;

    cudaFuncSetAttribute(attention_kernel,
                         cudaFuncAttributeMaxDynamicSharedMemorySize, SMEM_ATT3);
    cudaFuncSetAttribute(sort_kernel,
                         cudaFuncAttributeMaxDynamicSharedMemorySize, SMEM_SORT);
    cudaFuncSetAttribute(gemm_v_kernel,
                         cudaFuncAttributeMaxDynamicSharedMemorySize, SMEM_MMA);
    cudaFuncSetAttribute(bucket_kernel,
                         cudaFuncAttributeMaxDynamicSharedMemorySize, SMEM_BKT);

    split_w_kernel<<<dim3(16, 16), dim3(32, 8)>>>(W_V);

    dim3 qGrid(Dd / 128, (Nb * Tt) / 128);      // (4, 128)
    gemm_q_kernel<<<qGrid, 256>>>(x, W_Q, b_Q);

    dim3 vGrid(2, (Nb * Tt) / 128);             // (2, 128)
    gemm_v_kernel<<<vGrid, 512, SMEM_MMA>>>(x, b_V);

    dim3 bGrid(Tt / 128, Hh, Nb);               // (32, 8, 4)
    bucket_kernel<<<bGrid, 256, SMEM_BKT>>>(rot);

    sort_kernel<<<Nb * Hh, 256, SMEM_SORT>>>(); // 32 blocks

    dim3 aGrid(CSs, Hh, Nb);                    // (256, 8, 4)
    attention_kernel<<<aGrid, 128, SMEM_ATT3>>>();

    combine_ln_kernel<<<Nb * Tt, 128>>>(gamma, beta, out);
}